// round 6
// baseline (speedup 1.0000x reference)
#include <cuda_runtime.h>
#include <cstdint>

// Problem constants (dataset-fixed): B=64, T=512, F=1024, H=31, G=4H=124
#define B_SZ 64
#define T_SZ 512
#define F_SZ 1024
#define H_SZ 31
#define G_SZ 124
#define ROWS (B_SZ * T_SZ)      // 32768
#define XG_STRIDE 128           // padded gate stride

// ---------------- scratch (no allocations allowed) ----------------
__device__ float g_xg[(size_t)ROWS * XG_STRIDE];      // gates1 x-part + bias
__device__ float g_h2hist[(size_t)ROWS * 32];         // h2 per step, [b*T+t][32]

// ---------------- accurate activations (fast-math-proof) ----------------
__device__ __forceinline__ float exp_acc(float x) {
    x = fminf(fmaxf(x, -87.0f), 87.0f);
    float t = fmaf(x, 1.4426950408889634f, 12582912.0f);
    float kf = t - 12582912.0f;
    int k = (int)kf;
    float r = fmaf(kf, -0.693145751953125f, x);
    r = fmaf(kf, -1.42860676533018681e-6f, r);
    float p = 1.9841269841e-4f;
    p = fmaf(p, r, 1.3888888889e-3f);
    p = fmaf(p, r, 8.3333333333e-3f);
    p = fmaf(p, r, 4.1666666667e-2f);
    p = fmaf(p, r, 1.6666666667e-1f);
    p = fmaf(p, r, 0.5f);
    p = fmaf(p, r, 1.0f);
    p = fmaf(p, r, 1.0f);
    return p * __int_as_float((k + 127) << 23);
}

__device__ __forceinline__ float sigf(float x) {
    return __fdiv_rn(1.0f, 1.0f + exp_acc(-x));
}

__device__ __forceinline__ float tanh_acc(float x) {
    float ax = fabsf(x);
    if (ax < 0.625f) {
        float z = x * x;
        float p = -5.70498872745e-3f;
        p = fmaf(p, z, 2.06390887954e-2f);
        p = fmaf(p, z, -5.37397155531e-2f);
        p = fmaf(p, z, 1.33314422036e-1f);
        p = fmaf(p, z, -3.33332819422e-1f);
        return fmaf(x * z, p, x);
    } else {
        float e = exp_acc(2.0f * ax);
        float r = 1.0f - __fdiv_rn(2.0f, e + 1.0f);
        return copysignf(r, x);
    }
}

// =================================================================
// Kernel 1: xg[r][g] = input_row_r . W_ih1[g,:] + b_ih1[g] + b_hh1[g]
// M=32768, N=124(pad 128), K=1024. BM=64, BN=128, BK=32, 256 thr.
// =================================================================
__global__ __launch_bounds__(256) void gemm_xg_kernel(
    const float* __restrict__ x, const float* __restrict__ W,
    const float* __restrict__ b_ih, const float* __restrict__ b_hh) {
    __shared__ float xs[32][64];    // [k][row]
    __shared__ float ws[32][128];   // [k][col]

    const int tid = threadIdx.x;
    const int row0 = blockIdx.x * 64;
    const int rowg = tid >> 5;           // 0..7
    const int colg = tid & 31;           // 0..31
    const int rbase = rowg * 8;
    const int cbase = colg * 4;

    float acc[8][4];
#pragma unroll
    for (int i = 0; i < 8; i++)
#pragma unroll
        for (int j = 0; j < 4; j++) acc[i][j] = 0.0f;

    for (int k0 = 0; k0 < F_SZ; k0 += 32) {
#pragma unroll
        for (int l = tid; l < 512; l += 256) {
            int r = l >> 3;
            int kq = (l & 7) << 2;
            float4 v = *(const float4*)(x + (size_t)(row0 + r) * F_SZ + k0 + kq);
            xs[kq + 0][r] = v.x; xs[kq + 1][r] = v.y;
            xs[kq + 2][r] = v.z; xs[kq + 3][r] = v.w;
        }
#pragma unroll
        for (int l = tid; l < 1024; l += 256) {
            int g = l >> 3;
            int kq = (l & 7) << 2;
            float4 v = make_float4(0.f, 0.f, 0.f, 0.f);
            if (g < G_SZ) v = *(const float4*)(W + (size_t)g * F_SZ + k0 + kq);
            ws[kq + 0][g] = v.x; ws[kq + 1][g] = v.y;
            ws[kq + 2][g] = v.z; ws[kq + 3][g] = v.w;
        }
        __syncthreads();

#pragma unroll
        for (int kk = 0; kk < 32; kk++) {
            float4 wv = *(const float4*)&ws[kk][cbase];
            float4 xa = *(const float4*)&xs[kk][rbase];
            float4 xb = *(const float4*)&xs[kk][rbase + 4];
            float xr[8] = {xa.x, xa.y, xa.z, xa.w, xb.x, xb.y, xb.z, xb.w};
#pragma unroll
            for (int i = 0; i < 8; i++) {
                acc[i][0] = fmaf(xr[i], wv.x, acc[i][0]);
                acc[i][1] = fmaf(xr[i], wv.y, acc[i][1]);
                acc[i][2] = fmaf(xr[i], wv.z, acc[i][2]);
                acc[i][3] = fmaf(xr[i], wv.w, acc[i][3]);
            }
        }
        __syncthreads();
    }

    float bs[4];
#pragma unroll
    for (int c = 0; c < 4; c++) {
        int cc = cbase + c;
        bs[c] = (cc < G_SZ) ? (b_ih[cc] + b_hh[cc]) : 0.f;
    }
#pragma unroll
    for (int i = 0; i < 8; i++) {
        int r = row0 + rbase + i;
        float4 o = make_float4(acc[i][0] + bs[0], acc[i][1] + bs[1],
                               acc[i][2] + bs[2], acc[i][3] + bs[3]);
        *(float4*)&g_xg[(size_t)r * XG_STRIDE + cbase] = o;
    }
}

// =================================================================
// Kernel 2: recurrence (64 blocks = 1 per batch, 128 threads) +
//           in-block autoregressive future steps. Pure fp32.
// =================================================================
#define OFF_WLIN 0                      // 1024*31 = 31744
#define OFF_WHH1 31744                  // 124*31  = 3844
#define OFF_WIH2 35588
#define OFF_WHH2 39432
#define OFF_B2   43276                  // 124
#define OFF_B1F  43400                  // 124
#define OFF_BLIN 43524                  // 1024
#define OFF_G1   44548                  // 124
#define OFF_G2   44672                  // 124
#define OFF_H1   44796                  // 32
#define OFF_H2   44828                  // 32
#define OFF_XCUR 44860                  // 1024
#define SMEM_FLOATS 45884
#define SMEM_BYTES (SMEM_FLOATS * 4)

__global__ __launch_bounds__(128, 1) void recurrence_kernel(
    const float* __restrict__ W_hh1, const float* __restrict__ W_ih2,
    const float* __restrict__ W_hh2, const float* __restrict__ b_ih2,
    const float* __restrict__ b_hh2, const float* __restrict__ W_ih1,
    const float* __restrict__ b_ih1, const float* __restrict__ b_hh1,
    const float* __restrict__ W_lin, const float* __restrict__ b_lin,
    float* __restrict__ out, int Tout, int future) {
    extern __shared__ float sm[];
    float* wlins = sm + OFF_WLIN;
    float* whh1s = sm + OFF_WHH1;
    float* wih2s = sm + OFF_WIH2;
    float* whh2s = sm + OFF_WHH2;
    float* b2s   = sm + OFF_B2;
    float* b1fs  = sm + OFF_B1F;
    float* blins = sm + OFF_BLIN;
    float* g1s   = sm + OFF_G1;
    float* g2s   = sm + OFF_G2;
    float* h1s   = sm + OFF_H1;
    float* h2s   = sm + OFF_H2;
    float* xcur  = sm + OFF_XCUR;

    const int tid = threadIdx.x;
    const int b = blockIdx.x;
    const int g = tid;

    for (int i = tid; i < 31744; i += 128) wlins[i] = W_lin[i];
    for (int i = tid; i < 3844; i += 128) {
        whh1s[i] = W_hh1[i];
        wih2s[i] = W_ih2[i];
        whh2s[i] = W_hh2[i];
    }
    if (tid < G_SZ) {
        b2s[tid] = b_ih2[tid] + b_hh2[tid];
        b1fs[tid] = b_ih1[tid] + b_hh1[tid];
    }
    for (int i = tid; i < 1024; i += 128) blins[i] = b_lin[i];
    if (tid < 32) { h1s[tid] = 0.f; h2s[tid] = 0.f; }
    float c1 = 0.f, c2 = 0.f;
    __syncthreads();

    const float* xgp = g_xg + (size_t)b * T_SZ * XG_STRIDE + g;
    float cur = (g < G_SZ) ? __ldcg(xgp) : 0.f;

    // ---------------- teacher-forced recurrence ----------------
    for (int t = 0; t < T_SZ; t++) {
        float nxt = 0.f;
        if (g < G_SZ && t < T_SZ - 1) nxt = __ldcg(xgp + (size_t)(t + 1) * XG_STRIDE);

        if (g < G_SZ) {
            const float* w = whh1s + g * 31;
            float a0 = cur, a1 = 0.f, a2 = 0.f, a3 = 0.f;
#pragma unroll
            for (int k = 0; k < 28; k += 4) {
                a0 = fmaf(h1s[k + 0], w[k + 0], a0);
                a1 = fmaf(h1s[k + 1], w[k + 1], a1);
                a2 = fmaf(h1s[k + 2], w[k + 2], a2);
                a3 = fmaf(h1s[k + 3], w[k + 3], a3);
            }
            a0 = fmaf(h1s[28], w[28], a0);
            a1 = fmaf(h1s[29], w[29], a1);
            a2 = fmaf(h1s[30], w[30], a2);
            g1s[g] = (a0 + a1) + (a2 + a3);
        }
        __syncthreads();

        if (g < H_SZ) {
            float is = sigf(g1s[g]);
            float fs = sigf(g1s[31 + g]);
            float gg = tanh_acc(g1s[62 + g]);
            float os = sigf(g1s[93 + g]);
            c1 = fs * c1 + is * gg;
            h1s[g] = os * tanh_acc(c1);
        }
        __syncthreads();

        if (g < G_SZ) {
            const float* wa = wih2s + g * 31;
            const float* wb = whh2s + g * 31;
            float a0 = b2s[g], a1 = 0.f, a2 = 0.f, a3 = 0.f;
#pragma unroll
            for (int k = 0; k < 28; k += 2) {
                a0 = fmaf(h1s[k + 0], wa[k + 0], a0);
                a1 = fmaf(h2s[k + 0], wb[k + 0], a1);
                a2 = fmaf(h1s[k + 1], wa[k + 1], a2);
                a3 = fmaf(h2s[k + 1], wb[k + 1], a3);
            }
#pragma unroll
            for (int k = 28; k < 31; k++) {
                a0 = fmaf(h1s[k], wa[k], a0);
                a1 = fmaf(h2s[k], wb[k], a1);
            }
            g2s[g] = (a0 + a1) + (a2 + a3);
        }
        __syncthreads();

        if (g < H_SZ) {
            float is = sigf(g2s[g]);
            float fs = sigf(g2s[31 + g]);
            float gg = tanh_acc(g2s[62 + g]);
            float os = sigf(g2s[93 + g]);
            c2 = fs * c2 + is * gg;
            float h2 = os * tanh_acc(c2);
            h2s[g] = h2;
            g_h2hist[((size_t)b * T_SZ + t) * 32 + g] = h2;
        }
        cur = nxt;
        __syncthreads();
    }

    // ---------------- autoregressive future steps ----------------
    // xcur = output at t = T-1 (same value Phase-C writes to out[:,511,:])
#pragma unroll
    for (int i = 0; i < 8; i++) {
        int f = tid + i * 128;
        const float* w = wlins + f * 31;
        float a0 = blins[f], a1 = 0.f, a2 = 0.f, a3 = 0.f;
#pragma unroll
        for (int k = 0; k < 28; k += 4) {
            a0 = fmaf(h2s[k + 0], w[k + 0], a0);
            a1 = fmaf(h2s[k + 1], w[k + 1], a1);
            a2 = fmaf(h2s[k + 2], w[k + 2], a2);
            a3 = fmaf(h2s[k + 3], w[k + 3], a3);
        }
        a0 = fmaf(h2s[28], w[28], a0);
        a1 = fmaf(h2s[29], w[29], a1);
        a2 = fmaf(h2s[30], w[30], a2);
        xcur[f] = (a0 + a1) + (a2 + a3);
    }
    __syncthreads();

    for (int s = 1; s <= future; s++) {
        // gates1 = xcur . W_ih1^T + h1 . W_hh1^T + b1
        // (the h1.W_hh1 term was MISSING in rounds 1-5 — the structural bug)
        if (g < G_SZ) {
            // recurrent part first (smem)
            const float* wh = whh1s + g * 31;
            float r0 = b1fs[g], r1 = 0.f, r2 = 0.f, r3 = 0.f;
#pragma unroll
            for (int k = 0; k < 28; k += 4) {
                r0 = fmaf(h1s[k + 0], wh[k + 0], r0);
                r1 = fmaf(h1s[k + 1], wh[k + 1], r1);
                r2 = fmaf(h1s[k + 2], wh[k + 2], r2);
                r3 = fmaf(h1s[k + 3], wh[k + 3], r3);
            }
            r0 = fmaf(h1s[28], wh[28], r0);
            r1 = fmaf(h1s[29], wh[29], r1);
            r2 = fmaf(h1s[30], wh[30], r2);

            // input part: 1024-dim dot with W_ih1 row (L2 via ldcg)
            const float4* w4 = (const float4*)(W_ih1 + (size_t)g * F_SZ);
            const float4* x4 = (const float4*)xcur;
            float a0 = 0.f, a1 = 0.f, a2 = 0.f, a3 = 0.f;
#pragma unroll 8
            for (int q = 0; q < 256; q++) {
                float4 w = __ldcg(w4 + q);
                float4 xv = x4[q];
                a0 = fmaf(w.x, xv.x, a0);
                a1 = fmaf(w.y, xv.y, a1);
                a2 = fmaf(w.z, xv.z, a2);
                a3 = fmaf(w.w, xv.w, a3);
            }
            g1s[g] = ((a0 + a1) + (a2 + a3)) + ((r0 + r1) + (r2 + r3));
        }
        __syncthreads();

        if (g < H_SZ) {
            float is = sigf(g1s[g]);
            float fs = sigf(g1s[31 + g]);
            float gg = tanh_acc(g1s[62 + g]);
            float os = sigf(g1s[93 + g]);
            c1 = fs * c1 + is * gg;
            h1s[g] = os * tanh_acc(c1);
        }
        __syncthreads();

        if (g < G_SZ) {
            const float* wa = wih2s + g * 31;
            const float* wb = whh2s + g * 31;
            float a0 = b2s[g], a1 = 0.f, a2 = 0.f, a3 = 0.f;
#pragma unroll
            for (int k = 0; k < 28; k += 2) {
                a0 = fmaf(h1s[k + 0], wa[k + 0], a0);
                a1 = fmaf(h2s[k + 0], wb[k + 0], a1);
                a2 = fmaf(h1s[k + 1], wa[k + 1], a2);
                a3 = fmaf(h2s[k + 1], wb[k + 1], a3);
            }
#pragma unroll
            for (int k = 28; k < 31; k++) {
                a0 = fmaf(h1s[k], wa[k], a0);
                a1 = fmaf(h2s[k], wb[k], a1);
            }
            g2s[g] = (a0 + a1) + (a2 + a3);
        }
        __syncthreads();

        if (g < H_SZ) {
            float is = sigf(g2s[g]);
            float fs = sigf(g2s[31 + g]);
            float gg = tanh_acc(g2s[62 + g]);
            float os = sigf(g2s[93 + g]);
            c2 = fs * c2 + is * gg;
            h2s[g] = os * tanh_acc(c2);
        }
        __syncthreads();

        // out_{511+s} = h2 . W_lin^T + b_lin ; also becomes next x
#pragma unroll
        for (int i = 0; i < 8; i++) {
            int f = tid + i * 128;
            const float* w = wlins + f * 31;
            float a0 = blins[f], a1 = 0.f, a2 = 0.f, a3 = 0.f;
#pragma unroll
            for (int k = 0; k < 28; k += 4) {
                a0 = fmaf(h2s[k + 0], w[k + 0], a0);
                a1 = fmaf(h2s[k + 1], w[k + 1], a1);
                a2 = fmaf(h2s[k + 2], w[k + 2], a2);
                a3 = fmaf(h2s[k + 3], w[k + 3], a3);
            }
            a0 = fmaf(h2s[28], w[28], a0);
            a1 = fmaf(h2s[29], w[29], a1);
            a2 = fmaf(h2s[30], w[30], a2);
            float v = (a0 + a1) + (a2 + a3);
            xcur[f] = v;
            out[((size_t)b * Tout + (T_SZ - 1) + s) * F_SZ + f] = v;
        }
        __syncthreads();
    }
}

// =================================================================
// Kernel 3: teacher-forced output projection
// out[b,t,f] = h2hist[b,t,:] . W_lin[f,:] + b_lin[f]
// =================================================================
__global__ __launch_bounds__(256) void outproj_kernel(
    const float* __restrict__ W_lin, const float* __restrict__ b_lin,
    float* __restrict__ out, int Tout) {
    __shared__ float h2t[16][32];
    const int b = blockIdx.y;
    const int t0 = blockIdx.x * 16;
    const int tid = threadIdx.x;

    const float* src = g_h2hist + ((size_t)b * T_SZ + t0) * 32;
    for (int i = tid; i < 512; i += 256) ((float*)h2t)[i] = src[i];
    __syncthreads();

#pragma unroll
    for (int c = 0; c < 4; c++) {
        int f = tid + c * 256;
        float w[31];
        const float* wrow = W_lin + (size_t)f * 31;
#pragma unroll
        for (int k = 0; k < 31; k++) w[k] = wrow[k];
        float bv = b_lin[f];
#pragma unroll
        for (int tt = 0; tt < 16; tt++) {
            const float4* hp = (const float4*)&h2t[tt][0];
            float a0 = bv, a1 = 0.f, a2 = 0.f, a3 = 0.f;
#pragma unroll
            for (int q = 0; q < 7; q++) {
                float4 h = hp[q];
                a0 = fmaf(w[4 * q + 0], h.x, a0);
                a1 = fmaf(w[4 * q + 1], h.y, a1);
                a2 = fmaf(w[4 * q + 2], h.z, a2);
                a3 = fmaf(w[4 * q + 3], h.w, a3);
            }
            a0 = fmaf(w[28], h2t[tt][28], a0);
            a1 = fmaf(w[29], h2t[tt][29], a1);
            a2 = fmaf(w[30], h2t[tt][30], a2);
            out[((size_t)b * Tout + t0 + tt) * F_SZ + f] = (a0 + a1) + (a2 + a3);
        }
    }
}

// =================================================================
extern "C" void kernel_launch(void* const* d_in, const int* in_sizes, int n_in,
                              void* d_out, int out_size) {
    const float* input = (const float*)d_in[0];
    const float* W_ih1 = (const float*)d_in[1];
    const float* W_hh1 = (const float*)d_in[2];
    const float* b_ih1 = (const float*)d_in[3];
    const float* b_hh1 = (const float*)d_in[4];
    const float* W_ih2 = (const float*)d_in[5];
    const float* W_hh2 = (const float*)d_in[6];
    const float* b_ih2 = (const float*)d_in[7];
    const float* b_hh2 = (const float*)d_in[8];
    const float* W_lin = (const float*)d_in[9];
    const float* b_lin = (const float*)d_in[10];
    float* out = (float*)d_out;

    const int Tout = out_size / (B_SZ * F_SZ);   // 528
    const int future = Tout - T_SZ;              // 16

    cudaFuncSetAttribute(recurrence_kernel,
                         cudaFuncAttributeMaxDynamicSharedMemorySize, SMEM_BYTES);

    gemm_xg_kernel<<<ROWS / 64, 256>>>(input, W_ih1, b_ih1, b_hh1);

    recurrence_kernel<<<B_SZ, 128, SMEM_BYTES>>>(
        W_hh1, W_ih2, W_hh2, b_ih2, b_hh2, W_ih1, b_ih1, b_hh1,
        W_lin, b_lin, out, Tout, future);

    dim3 g3(T_SZ / 16, B_SZ);
    outproj_kernel<<<g3, 256>>>(W_lin, b_lin, out, Tout);
}